// round 1
// baseline (speedup 1.0000x reference)
#include <cuda_runtime.h>
#include <cstdint>

#define LOG2E 1.4426950408889634f
#define NPTS 4096

// Preprocessed operands (device globals: allocation-free scratch).
__device__ float g_U[16 * NPTS];   // U[d][i]  = x[i][d]/scale[d]               (d-major)
__device__ float g_V[16 * NPTS];   // V[d][j]  = log2e * xx[j][d]/scale[d]      (d-major)
__device__ float g_c[NPTS];        // c[i] = -0.5*log2e*||u_i||^2
__device__ float g_dv[NPTS];       // d[j] = -0.5*log2e*||v_j||^2 + log2(variance)

__global__ void rbf_preproc(const float* __restrict__ x,
                            const float* __restrict__ xx,
                            const float* __restrict__ scale_ff,
                            const float* __restrict__ var_ff) {
    int p = blockIdx.x * blockDim.x + threadIdx.x;
    if (p >= 2 * NPTS) return;

    float inv_s[16];
#pragma unroll
    for (int d = 0; d < 16; d++) {
        float s = log1pf(__expf(scale_ff[d]));   // softplus
        inv_s[d] = 1.0f / s;
    }
    float variance = log1pf(__expf(var_ff[0]));

    if (p < NPTS) {
        float s2 = 0.0f;
#pragma unroll
        for (int d = 0; d < 16; d++) {
            float u = x[p * 16 + d] * inv_s[d];
            g_U[d * NPTS + p] = u;
            s2 = fmaf(u, u, s2);
        }
        g_c[p] = -0.5f * LOG2E * s2;
    } else {
        int j = p - NPTS;
        float s2 = 0.0f;
#pragma unroll
        for (int d = 0; d < 16; d++) {
            float v = xx[j * 16 + d] * inv_s[d];
            g_V[d * NPTS + j] = LOG2E * v;
            s2 = fmaf(v, v, s2);
        }
        g_dv[j] = -0.5f * LOG2E * s2 + log2f(variance);
    }
}

// 128x128 tile per CTA, 256 threads, 8x8 outputs/thread (4+4 split per axis),
// packed fp32x2 FMA mainloop, MUFU.EX2 epilogue, float4 stores.
__global__ void __launch_bounds__(256, 2) rbf_main(float* __restrict__ out) {
    __shared__ __align__(16) float Ud[16][256];   // duplicated pairs: Ud[d][2i]=Ud[d][2i+1]=u
    __shared__ __align__(16) float Vs[16][128];
    __shared__ float cs[128];
    __shared__ float dsm[128];

    const int tid = threadIdx.x;
    const int tx = tid & 15;
    const int ty = tid >> 4;
    const int bi0 = blockIdx.y * 128;
    const int bj0 = blockIdx.x * 128;

    // ---- tile load (2048 U + 2048 V elements, coalesced) ----
#pragma unroll
    for (int s = 0; s < 8; s++) {
        int lin = tid + s * 256;          // 0..2047
        int d = lin >> 7;
        int i = lin & 127;
        float uu = g_U[d * NPTS + bi0 + i];
        Ud[d][2 * i]     = uu;
        Ud[d][2 * i + 1] = uu;
        Vs[d][i] = g_V[d * NPTS + bj0 + i];
    }
    if (tid < 128) {
        cs[tid]  = g_c[bi0 + tid];
        dsm[tid] = g_dv[bj0 + tid];
    }
    __syncthreads();

    // ---- accumulator init: acc = c_i + d_j (packed pairs over j) ----
    float cv[8], dv8[8];
#pragma unroll
    for (int r = 0; r < 4; r++) {
        cv[r]      = cs[ty * 4 + r];
        cv[4 + r]  = cs[64 + ty * 4 + r];
        dv8[r]     = dsm[tx * 4 + r];
        dv8[4 + r] = dsm[64 + tx * 4 + r];
    }
    unsigned long long acc[8][4];
#pragma unroll
    for (int ii = 0; ii < 8; ii++) {
#pragma unroll
        for (int jp = 0; jp < 4; jp++) {
            float lo = cv[ii] + dv8[2 * jp];
            float hi = cv[ii] + dv8[2 * jp + 1];
            asm("mov.b64 %0, {%1, %2};" : "=l"(acc[ii][jp]) : "f"(lo), "f"(hi));
        }
    }

    // ---- mainloop: D=16, fully unrolled; fma.rn.f32x2 ----
#pragma unroll
    for (int d = 0; d < 16; d++) {
        ulonglong2 u0 = *(const ulonglong2*)&Ud[d][8 * ty];         // dup(i0),dup(i1)
        ulonglong2 u1 = *(const ulonglong2*)&Ud[d][8 * ty + 4];     // dup(i2),dup(i3)
        ulonglong2 u2 = *(const ulonglong2*)&Ud[d][128 + 8 * ty];   // dup(i4),dup(i5)
        ulonglong2 u3 = *(const ulonglong2*)&Ud[d][128 + 8 * ty + 4];
        ulonglong2 va = *(const ulonglong2*)&Vs[d][4 * tx];         // (j0,j1),(j2,j3)
        ulonglong2 vb = *(const ulonglong2*)&Vs[d][64 + 4 * tx];    // (j4,j5),(j6,j7)

        unsigned long long du[8] = {u0.x, u0.y, u1.x, u1.y, u2.x, u2.y, u3.x, u3.y};
        unsigned long long vp[4] = {va.x, va.y, vb.x, vb.y};
#pragma unroll
        for (int ii = 0; ii < 8; ii++) {
#pragma unroll
            for (int jp = 0; jp < 4; jp++) {
                asm("fma.rn.f32x2 %0, %1, %2, %0;"
                    : "+l"(acc[ii][jp])
                    : "l"(du[ii]), "l"(vp[jp]));
            }
        }
    }

    // ---- epilogue: exp2 via MUFU.EX2, float4 stores ----
#pragma unroll
    for (int ii = 0; ii < 8; ii++) {
        int ig = bi0 + ((ii < 4) ? (ty * 4 + ii) : (64 + ty * 4 + (ii - 4)));
        float f[8];
#pragma unroll
        for (int jp = 0; jp < 4; jp++) {
            float lo, hi;
            asm("mov.b64 {%0, %1}, %2;" : "=f"(lo), "=f"(hi) : "l"(acc[ii][jp]));
            asm("ex2.approx.ftz.f32 %0, %0;" : "+f"(lo));
            asm("ex2.approx.ftz.f32 %0, %0;" : "+f"(hi));
            f[2 * jp]     = lo;
            f[2 * jp + 1] = hi;
        }
        float4 o0 = make_float4(f[0], f[1], f[2], f[3]);
        float4 o1 = make_float4(f[4], f[5], f[6], f[7]);
        *(float4*)&out[(size_t)ig * NPTS + bj0 + 4 * tx]      = o0;
        *(float4*)&out[(size_t)ig * NPTS + bj0 + 64 + 4 * tx] = o1;
    }
}

extern "C" void kernel_launch(void* const* d_in, const int* in_sizes, int n_in,
                              void* d_out, int out_size) {
    const float* x        = (const float*)d_in[0];   // [4096,16]
    const float* xx       = (const float*)d_in[1];   // [4096,16]
    const float* scale_ff = (const float*)d_in[2];   // [16]
    const float* var_ff   = (const float*)d_in[3];   // scalar

    float* out = (float*)d_out;                      // [4096,4096]

    rbf_preproc<<<(2 * NPTS + 255) / 256, 256>>>(x, xx, scale_ff, var_ff);
    dim3 grid(NPTS / 128, NPTS / 128);
    rbf_main<<<grid, 256>>>(out);
}